// round 5
// baseline (speedup 1.0000x reference)
#include <cuda_runtime.h>
#include <cuda_bf16.h>

// Problem constants (fixed shapes per reference)
#define N_NODES  100000
#define E_EDGES  1000000
#define IN_F     64
#define OUT_F    64
#define N_REL    16
#define N_BASES  8

#define CHUNK    2048
#define NCHUNKS  ((E_EDGES + CHUNK - 1) / CHUNK)   // 489
#define BATCH    6          // edges per warp-batch (3 pairs)
#define NPAIR    3
#define NC       27         // K3 segments per relation (27*16=432 CTAs ~ 148*3)

// ---------------------------------------------------------------------------
// Device scratch (static only — no cudaMalloc allowed)
// ---------------------------------------------------------------------------
// Basis-combined relation weights in 2x2-block layout (verified in R4):
//   float quad at d_W[r*4096 + (j*32+m)*4 + c]:
//     c=0: W[r][2j  ][2m  ]   c=1: W[r][2j+1][2m  ]
//     c=2: W[r][2j  ][2m+1]   c=3: W[r][2j+1][2m+1]
// ulonglong2 Wq = .x = {W[2j][2m],   W[2j+1][2m]}
//                 .y = {W[2j][2m+1], W[2j+1][2m+1]}
__device__ float d_W[N_REL * IN_F * OUT_F];
__device__ int   d_cnt[N_REL];
__device__ int   d_off[N_REL];
__device__ int   d_cur[N_REL];
__device__ int2  d_se[E_EDGES];     // edges sorted by relation: {src, dst}

// ---------------------------------------------------------------------------
// K1: basis combination (reference's reinterpreting-reshape quirk) into the
//     2x2-block layout. Also zeros d_cnt.
// ---------------------------------------------------------------------------
__global__ void compute_W_kernel(const float* __restrict__ weight,
                                 const float* __restrict__ w_comp) {
    int idx = blockIdx.x * blockDim.x + threadIdx.x;
    if (blockIdx.x == 0 && threadIdx.x < N_REL) d_cnt[threadIdx.x] = 0;
    if (idx >= N_REL * IN_F * OUT_F) return;
    int r  = idx >> 12;
    int j  = (idx >> 7) & 31;
    int l  = (idx >> 2) & 31;
    int c2 = idx & 3;
    int k  = 2 * j + (c2 & 1);
    int o  = 2 * l + (c2 >> 1);
    int t  = r * 4096 + k * 64 + o;     // W-flat index
    int im = t >> 10;                   // reinterpret as M-flat
    int rm = (t >> 6) & 15;
    int om = t & 63;
    float s = 0.f;
#pragma unroll
    for (int b = 0; b < N_BASES; b++)
        s += w_comp[rm * N_BASES + b] * weight[im * 512 + b * 64 + om];
    d_W[idx] = s;
}

// ---------------------------------------------------------------------------
__global__ void hist_kernel(const int* __restrict__ rel) {
    __shared__ int hc[N_REL];
    int tid = threadIdx.x;
    if (tid < N_REL) hc[tid] = 0;
    __syncthreads();
    int base = blockIdx.x * CHUNK;
#pragma unroll 2
    for (int j = tid; j < CHUNK; j += 256) {
        int e = base + j;
        if (e < E_EDGES) atomicAdd(&hc[rel[e]], 1);
    }
    __syncthreads();
    if (tid < N_REL) atomicAdd(&d_cnt[tid], hc[tid]);
}

__global__ void scan_kernel() {
    int t = threadIdx.x;
    int c = (t < N_REL) ? d_cnt[t] : 0;
    int v = c;
#pragma unroll
    for (int d = 1; d < N_REL; d <<= 1) {
        int u = __shfl_up_sync(0xffffffffu, v, d);
        if (t >= d) v += u;
    }
    if (t < N_REL) {
        int excl = v - c;
        d_off[t] = excl;
        d_cur[t] = excl;
    }
}

__global__ void sort_kernel(const int* __restrict__ src,
                            const int* __restrict__ dst,
                            const int* __restrict__ rel) {
    __shared__ int hc[N_REL];
    int tid = threadIdx.x;
    if (tid < N_REL) hc[tid] = 0;
    __syncthreads();
    int base = blockIdx.x * CHUNK;
#pragma unroll 2
    for (int j = tid; j < CHUNK; j += 256) {
        int e = base + j;
        if (e < E_EDGES) atomicAdd(&hc[rel[e]], 1);
    }
    __syncthreads();
    if (tid < N_REL) hc[tid] = atomicAdd(&d_cur[tid], hc[tid]);
    __syncthreads();
#pragma unroll 2
    for (int j = tid; j < CHUNK; j += 256) {
        int e = base + j;
        if (e < E_EDGES) {
            int p = atomicAdd(&hc[rel[e]], 1);
            d_se[p] = make_int2(src[e], dst[e]);
        }
    }
}

// ---------------------------------------------------------------------------
// K2: h_new = relu(h) into out[0 : N*64), zero out[N*64 : 2*N*64)
// ---------------------------------------------------------------------------
__global__ void relu_zero_kernel(const float4* __restrict__ h, float4* out) {
    int i = blockIdx.x * blockDim.x + threadIdx.x;
    const int n4 = N_NODES * IN_F / 4;
    if (i >= n4) return;
    float4 v = h[i];
    v.x = fmaxf(v.x, 0.f);
    v.y = fmaxf(v.y, 0.f);
    v.z = fmaxf(v.z, 0.f);
    v.w = fmaxf(v.w, 0.f);
    out[i] = v;
    out[n4 + i] = make_float4(0.f, 0.f, 0.f, 0.f);
}

// ---------------------------------------------------------------------------
// K3: sorted-edge message + scatter, SMEM-staged.
//   Warp batch = 6 edges = 3 pairs. Lanes 0-15 own edge 2p, lanes 16-31 own
//   edge 2p+1; each lane accumulates outputs {4l2 .. 4l2+3} (l2 = lane&15).
//   - h row staged to warp-private SMEM via coalesced LDG.64 (only L2 op)
//   - consumer: LDS.128 h (2 k-pairs) + 4 LDS.128 W per jj, pack-free f32x2
//   - scatter: one red.global.add.v4.f32 per lane per pair
// ---------------------------------------------------------------------------
__global__ void __launch_bounds__(256, 3)
scatter_msg_kernel(const float2* __restrict__ h2f,
                   float* __restrict__ h2,
                   int c_base) {
    __shared__ ulonglong2 Wq[32 * 32];            // 16 KB: W[r], 2x2-block
    __shared__ float2 stage[8][BATCH * 32];       // 12 KB: 8 warps x 6 rows

    const int r = blockIdx.y;
    const int c = c_base + blockIdx.x;
    const int start = d_off[r];
    const int cnt   = d_cnt[r];
    const int seg   = (cnt + NC - 1) / NC;
    const int s0    = start + c * seg;
    const int s1    = min(start + cnt, s0 + seg);

    const int tid = threadIdx.x;
    // Load W[r] into SMEM.
    {
        const ulonglong2* Wg = (const ulonglong2*)d_W + r * 1024;
#pragma unroll
        for (int i2 = tid; i2 < 1024; i2 += 256) Wq[i2] = Wg[i2];
    }
    __syncthreads();
    if (s0 >= s1) return;

    const int wid  = tid >> 5;
    const int lane = tid & 31;
    const int half = lane >> 4;          // 0: even edge of pair, 1: odd
    const int l2   = lane & 15;          // output group: o = 4*l2 .. 4*l2+3
    float2* st = stage[wid];

    for (int gb = s0 + wid * BATCH; gb < s1; gb += 8 * BATCH) {
        const int m = min(BATCH, s1 - gb);

        // Batch indices: lanes 0..m-1 hold {src,dst}; broadcast.
        int2 sd = make_int2(0, 0);
        if (lane < m) sd = __ldg(&d_se[gb + lane]);
        int sv[BATCH], dv[BATCH];
#pragma unroll
        for (int e = 0; e < BATCH; e++) {
            sv[e] = __shfl_sync(0xffffffffu, sd.x, e);
            dv[e] = __shfl_sync(0xffffffffu, sd.y, e);
        }
        // Clamp invalid tail edges to edge 0's src (valid row, scatter skipped)
#pragma unroll
        for (int e = 0; e < BATCH; e++) if (e >= m) sv[e] = sv[0];

        // Stage the 6 source rows: coalesced LDG.64, MLP=6, then STS.
        float2 tmp[BATCH];
#pragma unroll
        for (int e = 0; e < BATCH; e++)
            tmp[e] = __ldg(h2f + (long)sv[e] * 32 + lane);
        __syncwarp();
#pragma unroll
        for (int e = 0; e < BATCH; e++)
            st[e * 32 + lane] = tmp[e];
        __syncwarp();

        // Accumulators: per pair, E/O for o-pairs m0=2*l2 and m1=2*l2+1.
        unsigned long long aE0[NPAIR], aO0[NPAIR], aE1[NPAIR], aO1[NPAIR];
#pragma unroll
        for (int p = 0; p < NPAIR; p++) { aE0[p]=0; aO0[p]=0; aE1[p]=0; aO1[p]=0; }

#pragma unroll
        for (int jj = 0; jj < 16; jj++) {           // 4 k-values per jj
            // h: this lane's edge (2p+half), k = 4jj..4jj+3 as two b64 pairs
            ulonglong2 hq[NPAIR];
#pragma unroll
            for (int p = 0; p < NPAIR; p++)
                hq[p] = *(const ulonglong2*)(st + (2 * p + half) * 32 + jj * 2);
            // W 2x2 blocks for k-pairs j0=2jj, j1=2jj+1 and o-pairs m0,m1
            ulonglong2 w00 = Wq[(2 * jj) * 32 + 2 * l2];
            ulonglong2 w01 = Wq[(2 * jj) * 32 + 2 * l2 + 1];
            ulonglong2 w10 = Wq[(2 * jj + 1) * 32 + 2 * l2];
            ulonglong2 w11 = Wq[(2 * jj + 1) * 32 + 2 * l2 + 1];
#pragma unroll
            for (int p = 0; p < NPAIR; p++) {
                asm("fma.rn.f32x2 %0, %1, %2, %0;" : "+l"(aE0[p]) : "l"(hq[p].x), "l"(w00.x));
                asm("fma.rn.f32x2 %0, %1, %2, %0;" : "+l"(aO0[p]) : "l"(hq[p].x), "l"(w00.y));
                asm("fma.rn.f32x2 %0, %1, %2, %0;" : "+l"(aE1[p]) : "l"(hq[p].x), "l"(w01.x));
                asm("fma.rn.f32x2 %0, %1, %2, %0;" : "+l"(aO1[p]) : "l"(hq[p].x), "l"(w01.y));
                asm("fma.rn.f32x2 %0, %1, %2, %0;" : "+l"(aE0[p]) : "l"(hq[p].y), "l"(w10.x));
                asm("fma.rn.f32x2 %0, %1, %2, %0;" : "+l"(aO0[p]) : "l"(hq[p].y), "l"(w10.y));
                asm("fma.rn.f32x2 %0, %1, %2, %0;" : "+l"(aE1[p]) : "l"(hq[p].y), "l"(w11.x));
                asm("fma.rn.f32x2 %0, %1, %2, %0;" : "+l"(aO1[p]) : "l"(hq[p].y), "l"(w11.y));
            }
        }

        // Scatter: out[4*l2 + {0,1,2,3}] for edge 2p+half.
#pragma unroll
        for (int p = 0; p < NPAIR; p++) {
            int eidx = 2 * p + half;
            if (eidx < m) {
                float x0, x1, y0, y1, z0, z1, u0, u1;
                asm("mov.b64 {%0, %1}, %2;" : "=f"(x0), "=f"(x1) : "l"(aE0[p]));
                asm("mov.b64 {%0, %1}, %2;" : "=f"(y0), "=f"(y1) : "l"(aO0[p]));
                asm("mov.b64 {%0, %1}, %2;" : "=f"(z0), "=f"(z1) : "l"(aE1[p]));
                asm("mov.b64 {%0, %1}, %2;" : "=f"(u0), "=f"(u1) : "l"(aO1[p]));
                float o0 = x0 + x1;
                float o1 = y0 + y1;
                float o2 = z0 + z1;
                float o3 = u0 + u1;
                float* pdst = h2 + (long)dv[eidx] * 64 + 4 * l2;
                asm volatile("red.global.add.v4.f32 [%0], {%1, %2, %3, %4};"
                             :: "l"(pdst), "f"(o0), "f"(o1), "f"(o2), "f"(o3)
                             : "memory");
            }
        }
        __syncwarp();   // protect stage before next batch's STS
    }
}

// ---------------------------------------------------------------------------
extern "C" void kernel_launch(void* const* d_in, const int* in_sizes, int n_in,
                              void* d_out, int out_size) {
    const float* h      = (const float*)d_in[0];
    const float* weight = (const float*)d_in[1];
    const float* w_comp = (const float*)d_in[2];
    const int*   src    = (const int*)d_in[3];
    const int*   dst    = (const int*)d_in[4];
    const int*   rel    = (const int*)d_in[5];
    float* out = (float*)d_out;          // [h_new (N*64) | h2 (N*64)]
    float* h2  = out + N_NODES * IN_F;

    // K1: basis combination into 2x2-block d_W (+ zero d_cnt)
    compute_W_kernel<<<(N_REL * IN_F * OUT_F + 255) / 256, 256>>>(weight, w_comp);

    // Counting sort by relation
    hist_kernel<<<NCHUNKS, 256>>>(rel);
    scan_kernel<<<1, 32>>>();
    sort_kernel<<<NCHUNKS, 256>>>(src, dst, rel);

    // K2: relu(h) -> out, zero h2
    relu_zero_kernel<<<(N_NODES * IN_F / 4 + 255) / 256, 256>>>(
        (const float4*)h, (float4*)out);

    // K3: edge messages + scatter (split so an ncu capture slot lands here)
    dim3 gridA(14, N_REL);
    dim3 gridB(NC - 14, N_REL);
    scatter_msg_kernel<<<gridA, 256>>>((const float2*)h, h2, 0);
    scatter_msg_kernel<<<gridB, 256>>>((const float2*)h, h2, 14);
}

// round 6
// speedup vs baseline: 1.5003x; 1.5003x over previous
#include <cuda_runtime.h>
#include <cuda_bf16.h>

// Problem constants (fixed shapes per reference)
#define N_NODES  100000
#define E_EDGES  1000000
#define IN_F     64
#define OUT_F    64
#define N_REL    16
#define N_BASES  8

#define CHUNK    2048
#define NCHUNKS  ((E_EDGES + CHUNK - 1) / CHUNK)   // 489
#define BATCH    8
#define NC       18        // K3 segments per relation: 18*16 = 288 CTAs = 1 wave @2/SM

// ---------------------------------------------------------------------------
// Device scratch (static only — no cudaMalloc allowed)
// ---------------------------------------------------------------------------
// Basis-combined relation weights in 2x2-block layout (verified R4):
//   ulonglong2 Wq[r][j*32+m]:
//     .x = {W[r][2j][2m],   W[r][2j+1][2m]}
//     .y = {W[r][2j][2m+1], W[r][2j+1][2m+1]}
__device__ float d_W[N_REL * IN_F * OUT_F];
__device__ int   d_cnt[N_REL];        // zero-init; reset by scan CTA each call
__device__ int   d_done;              // zero-init; reset by scan CTA each call
__device__ int   d_off[N_REL + 1];
__device__ int   d_cur[N_REL];
__device__ int2  d_se[E_EDGES];       // edges sorted by relation: {src, dst}

// ---------------------------------------------------------------------------
// L0: fused kernel.
//   blocks [0,256):    basis combination into 2x2-block d_W (reference's
//                      reinterpreting-reshape quirk preserved).
//   blocks [256,745):  rel histogram into d_cnt; the LAST hist CTA performs
//                      the 16-element exclusive scan -> d_off/d_cur and
//                      resets d_cnt/d_done for the next graph replay.
// ---------------------------------------------------------------------------
__global__ void w_hist_scan_kernel(const float* __restrict__ weight,
                                   const float* __restrict__ w_comp,
                                   const int* __restrict__ rel) {
    const int tid = threadIdx.x;
    if (blockIdx.x < 256) {
        int idx = blockIdx.x * 256 + tid;
        int r  = idx >> 12;
        int j  = (idx >> 7) & 31;
        int l  = (idx >> 2) & 31;
        int c2 = idx & 3;
        int k  = 2 * j + (c2 & 1);
        int o  = 2 * l + (c2 >> 1);
        int t  = r * 4096 + k * 64 + o;     // W-flat index
        int im = t >> 10;                   // reinterpret as M-flat
        int rm = (t >> 6) & 15;
        int om = t & 63;
        float s = 0.f;
#pragma unroll
        for (int b = 0; b < N_BASES; b++)
            s += w_comp[rm * N_BASES + b] * weight[im * 512 + b * 64 + om];
        d_W[idx] = s;
        return;
    }

    // ---- histogram part ----
    __shared__ int hc[N_REL];
    __shared__ int is_last;
    if (tid < N_REL) hc[tid] = 0;
    if (tid == 0) is_last = 0;
    __syncthreads();
    int base = (blockIdx.x - 256) * CHUNK;
#pragma unroll 2
    for (int j = tid; j < CHUNK; j += 256) {
        int e = base + j;
        if (e < E_EDGES) atomicAdd(&hc[rel[e]], 1);
    }
    __syncthreads();
    if (tid < N_REL) atomicAdd(&d_cnt[tid], hc[tid]);
    __threadfence();
    if (tid == 0) {
        int prev = atomicAdd(&d_done, 1);
        if (prev == NCHUNKS - 1) is_last = 1;
    }
    __syncthreads();
    if (is_last && tid < 32) {
        int c = (tid < N_REL) ? atomicAdd(&d_cnt[tid], 0) : 0;
        int v = c;
#pragma unroll
        for (int d = 1; d < N_REL; d <<= 1) {
            int u = __shfl_up_sync(0xffffffffu, v, d);
            if (tid >= d) v += u;
        }
        if (tid < N_REL) {
            int excl = v - c;
            d_off[tid] = excl;
            d_cur[tid] = excl;
            d_cnt[tid] = 0;            // reset for next replay
        }
        if (tid == 0) {
            d_off[N_REL] = E_EDGES;
            d_done = 0;                // reset for next replay
        }
    }
}

// ---------------------------------------------------------------------------
// L1: counting-sort scatter by relation.
// ---------------------------------------------------------------------------
__global__ void sort_kernel(const int* __restrict__ src,
                            const int* __restrict__ dst,
                            const int* __restrict__ rel) {
    __shared__ int hc[N_REL];
    int tid = threadIdx.x;
    if (tid < N_REL) hc[tid] = 0;
    __syncthreads();
    int base = blockIdx.x * CHUNK;
#pragma unroll 2
    for (int j = tid; j < CHUNK; j += 256) {
        int e = base + j;
        if (e < E_EDGES) atomicAdd(&hc[rel[e]], 1);
    }
    __syncthreads();
    if (tid < N_REL) hc[tid] = atomicAdd(&d_cur[tid], hc[tid]);
    __syncthreads();
#pragma unroll 2
    for (int j = tid; j < CHUNK; j += 256) {
        int e = base + j;
        if (e < E_EDGES) {
            int p = atomicAdd(&hc[rel[e]], 1);
            d_se[p] = make_int2(src[e], dst[e]);
        }
    }
}

// ---------------------------------------------------------------------------
// L2: h_new = relu(h) into out[0 : N*64), zero out[N*64 : 2*N*64)
// ---------------------------------------------------------------------------
__global__ void relu_zero_kernel(const float4* __restrict__ h, float4* out) {
    int i = blockIdx.x * blockDim.x + threadIdx.x;
    const int n4 = N_NODES * IN_F / 4;
    if (i >= n4) return;
    float4 v = h[i];
    v.x = fmaxf(v.x, 0.f);
    v.y = fmaxf(v.y, 0.f);
    v.z = fmaxf(v.z, 0.f);
    v.w = fmaxf(v.w, 0.f);
    out[i] = v;
    out[n4 + i] = make_float4(0.f, 0.f, 0.f, 0.f);
}

// ---------------------------------------------------------------------------
// L3: sorted-edge message + scatter (R2/R4-proven mainloop).
//   grid = (NC, 16). CTA (c, r): W[r] in SMEM (2x2-block), segment c of
//   relation r's sorted edges. Warps: 8 edges/batch:
//     - h pairs {h[k],h[k+1]} via uniform LDG.128 (direct f32x2 operand)
//     - 2 LDS.128 of W per jj (4 k-values)
//     - pack-free fma.rn.f32x2 into E/O accumulators
//     - scatter: shfl-pair then red.global.add.v4.f32 from even lanes
// ---------------------------------------------------------------------------
__global__ void __launch_bounds__(256, 2)
scatter_msg_kernel(const ulonglong2* __restrict__ h2v,
                   float* __restrict__ h2) {
    __shared__ ulonglong2 Wq[32 * 32];   // 16 KB

    const int r = blockIdx.y;
    const int c = blockIdx.x;
    const int start = d_off[r];
    const int cnt   = d_off[r + 1] - start;
    const int seg   = (cnt + NC - 1) / NC;
    const int s0    = start + c * seg;
    const int s1    = min(start + cnt, s0 + seg);

    const int tid = threadIdx.x;
    {
        const ulonglong2* Wg = (const ulonglong2*)d_W + r * 1024;
#pragma unroll
        for (int i2 = tid; i2 < 1024; i2 += 256) Wq[i2] = Wg[i2];
    }
    __syncthreads();
    if (s0 >= s1) return;

    const int wid  = tid >> 5;
    const int lane = tid & 31;

    for (int gb = s0 + wid * BATCH; gb < s1; gb += 8 * BATCH) {
        const int m = min(BATCH, s1 - gb);

        // Lanes 0..m-1 hold {src,dst}; broadcast to all lanes.
        int2 sd = make_int2(0, 0);
        if (lane < m) sd = __ldg(&d_se[gb + lane]);
        const ulonglong2* pe[BATCH];
        int dv[BATCH];
#pragma unroll
        for (int e = 0; e < BATCH; e++) {
            int se = __shfl_sync(0xffffffffu, sd.x, e);
            dv[e]  = __shfl_sync(0xffffffffu, sd.y, e);
            pe[e]  = h2v + (long)se * 16;    // 64 floats = 16 x 16B
        }

        unsigned long long accE[BATCH], accO[BATCH];
#pragma unroll
        for (int e = 0; e < BATCH; e++) { accE[e] = 0ull; accO[e] = 0ull; }

#pragma unroll
        for (int jj = 0; jj < 16; jj++) {        // 4 k-values per jj
            ulonglong2 hp[BATCH];
#pragma unroll
            for (int e = 0; e < BATCH; e++)
                hp[e] = __ldg(pe[e] + jj);       // {h4jj,h4jj+1 | h4jj+2,h4jj+3}
            ulonglong2 w0 = Wq[(2 * jj) * 32 + lane];
            ulonglong2 w1 = Wq[(2 * jj + 1) * 32 + lane];
#pragma unroll
            for (int e = 0; e < BATCH; e++) {
                asm("fma.rn.f32x2 %0, %1, %2, %0;" : "+l"(accE[e]) : "l"(hp[e].x), "l"(w0.x));
                asm("fma.rn.f32x2 %0, %1, %2, %0;" : "+l"(accO[e]) : "l"(hp[e].x), "l"(w0.y));
                asm("fma.rn.f32x2 %0, %1, %2, %0;" : "+l"(accE[e]) : "l"(hp[e].y), "l"(w1.x));
                asm("fma.rn.f32x2 %0, %1, %2, %0;" : "+l"(accO[e]) : "l"(hp[e].y), "l"(w1.y));
            }
        }

        // Scatter: lane owns outputs {2l, 2l+1}. Pair lanes (l even | l+1)
        // to form 4 consecutive outputs -> one red.v4 from even lanes.
#pragma unroll
        for (int e = 0; e < BATCH; e++) {
            float x0, x1, y0, y1;
            asm("mov.b64 {%0, %1}, %2;" : "=f"(x0), "=f"(x1) : "l"(accE[e]));
            asm("mov.b64 {%0, %1}, %2;" : "=f"(y0), "=f"(y1) : "l"(accO[e]));
            float o0 = x0 + x1;               // output 2*lane
            float o1 = y0 + y1;               // output 2*lane+1
            float o2 = __shfl_down_sync(0xffffffffu, o0, 1);
            float o3 = __shfl_down_sync(0xffffffffu, o1, 1);
            if ((lane & 1) == 0 && e < m) {
                float* p = h2 + (long)dv[e] * 64 + 2 * lane;
                asm volatile("red.global.add.v4.f32 [%0], {%1, %2, %3, %4};"
                             :: "l"(p), "f"(o0), "f"(o1), "f"(o2), "f"(o3)
                             : "memory");
            }
        }
    }
}

// ---------------------------------------------------------------------------
extern "C" void kernel_launch(void* const* d_in, const int* in_sizes, int n_in,
                              void* d_out, int out_size) {
    const float* h      = (const float*)d_in[0];
    const float* weight = (const float*)d_in[1];
    const float* w_comp = (const float*)d_in[2];
    const int*   src    = (const int*)d_in[3];
    const int*   dst    = (const int*)d_in[4];
    const int*   rel    = (const int*)d_in[5];
    float* out = (float*)d_out;          // [h_new (N*64) | h2 (N*64)]
    float* h2  = out + N_NODES * IN_F;

    // Launch 0: W basis-combination + rel histogram + fused scan
    w_hist_scan_kernel<<<256 + NCHUNKS, 256>>>(weight, w_comp, rel);
    // Launch 1: counting-sort by relation
    sort_kernel<<<NCHUNKS, 256>>>(src, dst, rel);
    // Launch 2: relu(h) -> out, zero h2
    relu_zero_kernel<<<(N_NODES * IN_F / 4 + 255) / 256, 256>>>(
        (const float4*)h, (float4*)out);
    // Launch 3: edge messages + scatter  (ncu capture slot = launch index 3)
    dim3 grid(NC, N_REL);
    scatter_msg_kernel<<<grid, 256>>>((const ulonglong2*)h, h2);
}

// round 8
// speedup vs baseline: 2.5538x; 1.7022x over previous
#include <cuda_runtime.h>
#include <cuda_bf16.h>

// Problem constants (fixed shapes per reference)
#define N_NODES  100000
#define E_EDGES  1000000
#define N_REL    16
#define N_BASES  8
#define CHUNK    2048
#define NCHUNKS  489
#define NC       18          // segments per relation: 18*16 = 288 CTAs (1 wave @2/SM)
#define TILE_M   128

// SMEM layout (bytes). Rows padded to 144 B (72 bf16) => conflict-free LDSM/LDS.
#define A_STRIDE 144
#define SM_AHI   0                         // 128 x 144 = 18432
#define SM_ALO   18432                     // 18432
#define SM_BHI   36864                     // 64 x 144 = 9216  (B[n][k])
#define SM_BLO   46080                     // 9216
#define SM_DST   55296                     // 128 ints = 512
#define SM_BYTES 55808

// ---------------------------------------------------------------------------
// Device scratch (static only — no cudaMalloc allowed)
// ---------------------------------------------------------------------------
__device__ float d_W[N_REL * 64 * 64];   // W[r][k][o] at r*4096 + k*64 + o
__device__ int   d_cnt[N_REL];           // zero-init; reset each replay
__device__ int   d_done;                 // zero-init; reset each replay
__device__ int   d_off[N_REL + 1];
__device__ int   d_cur[N_REL];
__device__ int2  d_se[E_EDGES];          // edges sorted by relation {src,dst}

// ---------------------------------------------------------------------------
__device__ __forceinline__ unsigned smem_u32(const void* p) {
    unsigned r;
    asm("{ .reg .u64 t; cvta.to.shared.u64 t, %1; cvt.u32.u64 %0, t; }"
        : "=r"(r) : "l"(p));
    return r;
}
__device__ __forceinline__ unsigned pk2(__nv_bfloat16 a, __nv_bfloat16 b) {
    unsigned short ua = *(unsigned short*)&a, ub = *(unsigned short*)&b;
    return (unsigned)ua | ((unsigned)ub << 16);
}
__device__ __forceinline__ void split2(float x, float y, unsigned& hi, unsigned& lo) {
    __nv_bfloat16 xh = __float2bfloat16_rn(x), yh = __float2bfloat16_rn(y);
    __nv_bfloat16 xl = __float2bfloat16_rn(x - __bfloat162float(xh));
    __nv_bfloat16 yl = __float2bfloat16_rn(y - __bfloat162float(yh));
    hi = pk2(xh, yh);
    lo = pk2(xl, yl);
}
__device__ __forceinline__ void ldsm_x4(unsigned a[4], unsigned addr) {
    asm volatile("ldmatrix.sync.aligned.m8n8.x4.shared.b16 {%0,%1,%2,%3}, [%4];"
                 : "=r"(a[0]), "=r"(a[1]), "=r"(a[2]), "=r"(a[3]) : "r"(addr));
}
__device__ __forceinline__ void mma_bf16(float c[4], const unsigned a[4],
                                         unsigned b0, unsigned b1) {
    asm volatile(
        "mma.sync.aligned.m16n8k16.row.col.f32.bf16.bf16.f32 "
        "{%0,%1,%2,%3}, {%4,%5,%6,%7}, {%8,%9}, {%0,%1,%2,%3};"
        : "+f"(c[0]), "+f"(c[1]), "+f"(c[2]), "+f"(c[3])
        : "r"(a[0]), "r"(a[1]), "r"(a[2]), "r"(a[3]), "r"(b0), "r"(b1));
}

// ---------------------------------------------------------------------------
// L0: fused W basis-combination + rel histogram + scan (proven R6).
// ---------------------------------------------------------------------------
__global__ void w_hist_scan_kernel(const float* __restrict__ weight,
                                   const float* __restrict__ w_comp,
                                   const int* __restrict__ rel) {
    const int tid = threadIdx.x;
    if (blockIdx.x < 256) {
        int idx = blockIdx.x * 256 + tid;
        int im = idx >> 10;
        int rm = (idx >> 6) & 15;
        int om = idx & 63;
        float s = 0.f;
#pragma unroll
        for (int b = 0; b < N_BASES; b++)
            s += w_comp[rm * N_BASES + b] * weight[im * 512 + b * 64 + om];
        d_W[idx] = s;
        return;
    }
    __shared__ int hc[N_REL];
    __shared__ int is_last;
    if (tid < N_REL) hc[tid] = 0;
    if (tid == 0) is_last = 0;
    __syncthreads();
    int base = (blockIdx.x - 256) * CHUNK;
#pragma unroll 2
    for (int j = tid; j < CHUNK; j += 256) {
        int e = base + j;
        if (e < E_EDGES) atomicAdd(&hc[rel[e]], 1);
    }
    __syncthreads();
    if (tid < N_REL) atomicAdd(&d_cnt[tid], hc[tid]);
    __threadfence();
    if (tid == 0) {
        int prev = atomicAdd(&d_done, 1);
        if (prev == NCHUNKS - 1) is_last = 1;
    }
    __syncthreads();
    if (is_last && tid < 32) {
        int c = (tid < N_REL) ? atomicAdd(&d_cnt[tid], 0) : 0;
        int v = c;
#pragma unroll
        for (int d = 1; d < N_REL; d <<= 1) {
            int u = __shfl_up_sync(0xffffffffu, v, d);
            if (tid >= d) v += u;
        }
        if (tid < N_REL) {
            int excl = v - c;
            d_off[tid] = excl;
            d_cur[tid] = excl;
            d_cnt[tid] = 0;
        }
        if (tid == 0) {
            d_off[N_REL] = E_EDGES;
            d_done = 0;
        }
    }
}

// ---------------------------------------------------------------------------
// L1: counting-sort scatter by relation (proven).
// ---------------------------------------------------------------------------
__global__ void sort_kernel(const int* __restrict__ src,
                            const int* __restrict__ dst,
                            const int* __restrict__ rel) {
    __shared__ int hc[N_REL];
    int tid = threadIdx.x;
    if (tid < N_REL) hc[tid] = 0;
    __syncthreads();
    int base = blockIdx.x * CHUNK;
#pragma unroll 2
    for (int j = tid; j < CHUNK; j += 256) {
        int e = base + j;
        if (e < E_EDGES) atomicAdd(&hc[rel[e]], 1);
    }
    __syncthreads();
    if (tid < N_REL) hc[tid] = atomicAdd(&d_cur[tid], hc[tid]);
    __syncthreads();
#pragma unroll 2
    for (int j = tid; j < CHUNK; j += 256) {
        int e = base + j;
        if (e < E_EDGES) {
            int p = atomicAdd(&hc[rel[e]], 1);
            d_se[p] = make_int2(src[e], dst[e]);
        }
    }
}

// ---------------------------------------------------------------------------
// L2: h_new = relu(h); zero h2 accumulator.
// ---------------------------------------------------------------------------
__global__ void relu_zero_kernel(const float4* __restrict__ h, float4* out) {
    int i = blockIdx.x * blockDim.x + threadIdx.x;
    const int n4 = N_NODES * 64 / 4;
    if (i >= n4) return;
    float4 v = h[i];
    v.x = fmaxf(v.x, 0.f);
    v.y = fmaxf(v.y, 0.f);
    v.z = fmaxf(v.z, 0.f);
    v.w = fmaxf(v.w, 0.f);
    out[i] = v;
    out[n4 + i] = make_float4(0.f, 0.f, 0.f, 0.f);
}

// ---------------------------------------------------------------------------
// L3: HMMA tile GEMM + scatter (mma.sync m16n8k16 bf16, split hi/lo).
//   CTA (c, r): B = W[r] as [n][k] hi/lo in SMEM (once). Tiles of 128 edges:
//   all warps gather 16 rows each -> A hi/lo SMEM; warp w computes rows
//   (w&3)*32..+31 x cols (w>>2)*32..+31 with 3-product bf16 split into fp32
//   C fragments; epilogue shfl-pairs and red.global.add.v4.f32.
// ---------------------------------------------------------------------------
__global__ void __launch_bounds__(256, 2)
mma_scatter_kernel(const float4* __restrict__ h4, float* __restrict__ h2) {
    extern __shared__ __align__(16) char dsm[];
    const unsigned sb = smem_u32(dsm);

    const int r = blockIdx.y;
    const int c = blockIdx.x;
    const int start = d_off[r];
    const int cnt   = d_off[r + 1] - start;
    const int seg   = (cnt + NC - 1) / NC;
    const int s0    = start + c * seg;
    const int s1    = min(start + cnt, s0 + seg);

    const int tid  = threadIdx.x;
    const int wid  = tid >> 5;
    const int lane = tid & 31;
    const int g    = lane >> 2;      // fragment row group
    const int t    = lane & 3;       // fragment col group

    // ---- stage B = W[r] as [n][k] bf16 hi/lo, padded rows ----
    for (int idx = tid; idx < 2048; idx += 256) {
        int k2 = idx >> 6;           // k pair index (k = 2*k2, 2*k2+1)
        int o  = idx & 63;           // n
        float x0 = d_W[r * 4096 + (2 * k2) * 64 + o];
        float x1 = d_W[r * 4096 + (2 * k2 + 1) * 64 + o];
        unsigned hi, lo;
        split2(x0, x1, hi, lo);
        *(unsigned*)(dsm + SM_BHI + o * A_STRIDE + k2 * 4) = hi;
        *(unsigned*)(dsm + SM_BLO + o * A_STRIDE + k2 * 4) = lo;
    }
    __syncthreads();
    if (s0 >= s1) return;

    const int rowblk = (wid & 3) * 32;   // this warp's 32 edge-rows
    const int nhalf  = wid >> 2;         // this warp's 32-col half
    // A ldmatrix lane address components (row = lane&15, khalf = lane>>4)
    const unsigned a_lane_off = (unsigned)((lane & 15) * A_STRIDE + ((lane >> 4) & 1) * 16);

    for (int tb = s0; tb < s1; tb += TILE_M) {
        const int mt = min(TILE_M, s1 - tb);

        // ---- gather: warp wid stages rows wid*16 .. wid*16+15 ----
        {
            int grow = wid * 16 + (lane >> 1);
            int half = lane & 1;
            int eidx = min(tb + grow, s1 - 1);
            int2 sd  = __ldg(&d_se[eidx]);
            if (half == 0) *(int*)(dsm + SM_DST + grow * 4) = sd.y;
            const float4* hp = h4 + (long)sd.x * 16 + half * 8;
            unsigned abase = grow * A_STRIDE + half * 64;  // 32 bf16 = 64 B
#pragma unroll
            for (int i = 0; i < 4; i++) {
                float4 a = __ldg(hp + 2 * i);
                float4 b = __ldg(hp + 2 * i + 1);
                uint4 H, L;
                split2(a.x, a.y, H.x, L.x);
                split2(a.z, a.w, H.y, L.y);
                split2(b.x, b.y, H.z, L.z);
                split2(b.z, b.w, H.w, L.w);
                *(uint4*)(dsm + SM_AHI + abase + i * 16) = H;
                *(uint4*)(dsm + SM_ALO + abase + i * 16) = L;
            }
        }
        __syncthreads();

        // ---- MMA: C[2 mtiles][4 nblk][4] ----
        float cf[2][4][4];
#pragma unroll
        for (int m = 0; m < 2; m++)
#pragma unroll
            for (int nb = 0; nb < 4; nb++)
#pragma unroll
                for (int q = 0; q < 4; q++) cf[m][nb][q] = 0.f;

#pragma unroll
        for (int kb = 0; kb < 4; kb++) {
            // B fragments for this kblk (direct LDS per PTX fragment map)
            unsigned bh[4][2], bl[4][2];
#pragma unroll
            for (int nb = 0; nb < 4; nb++) {
                unsigned boff = (unsigned)((nhalf * 32 + nb * 8 + g) * A_STRIDE
                                           + (kb * 16 + 2 * t) * 2);
                bh[nb][0] = *(const unsigned*)(dsm + SM_BHI + boff);
                bh[nb][1] = *(const unsigned*)(dsm + SM_BHI + boff + 16);
                bl[nb][0] = *(const unsigned*)(dsm + SM_BLO + boff);
                bl[nb][1] = *(const unsigned*)(dsm + SM_BLO + boff + 16);
            }
#pragma unroll
            for (int m = 0; m < 2; m++) {
                unsigned ah[4], al[4];
                unsigned aaddr = sb + (unsigned)((rowblk + m * 16) * A_STRIDE + kb * 32)
                               + a_lane_off;
                ldsm_x4(ah, aaddr + SM_AHI);
                ldsm_x4(al, aaddr + SM_ALO);
#pragma unroll
                for (int nb = 0; nb < 4; nb++) {
                    mma_bf16(cf[m][nb], ah, bh[nb][0], bh[nb][1]);
                    mma_bf16(cf[m][nb], al, bh[nb][0], bh[nb][1]);
                    mma_bf16(cf[m][nb], ah, bl[nb][0], bl[nb][1]);
                }
            }
        }

        // ---- epilogue: shfl-pair -> red.global.add.v4.f32 ----
#pragma unroll
        for (int m = 0; m < 2; m++) {
            int row0 = rowblk + m * 16 + g;      // tile-local edge row
            int row8 = row0 + 8;
            int d0 = *(const int*)(dsm + SM_DST + row0 * 4);
            int d8 = *(const int*)(dsm + SM_DST + row8 * 4);
#pragma unroll
            for (int nb = 0; nb < 4; nb++) {
                float o0 = cf[m][nb][0], o1 = cf[m][nb][1];
                float p0 = cf[m][nb][2], p1 = cf[m][nb][3];
                float o2 = __shfl_down_sync(0xffffffffu, o0, 1);
                float o3 = __shfl_down_sync(0xffffffffu, o1, 1);
                float p2 = __shfl_down_sync(0xffffffffu, p0, 1);
                float p3 = __shfl_down_sync(0xffffffffu, p1, 1);
                if ((t & 1) == 0) {
                    int col = nhalf * 32 + nb * 8 + 2 * t;
                    if (row0 < mt) {
                        float* p = h2 + (long)d0 * 64 + col;
                        asm volatile("red.global.add.v4.f32 [%0], {%1,%2,%3,%4};"
                                     :: "l"(p), "f"(o0), "f"(o1), "f"(o2), "f"(o3)
                                     : "memory");
                    }
                    if (row8 < mt) {
                        float* p = h2 + (long)d8 * 64 + col;
                        asm volatile("red.global.add.v4.f32 [%0], {%1,%2,%3,%4};"
                                     :: "l"(p), "f"(p0), "f"(p1), "f"(p2), "f"(p3)
                                     : "memory");
                    }
                }
            }
        }
        __syncthreads();   // protect A/dst stage before next gather
    }
}

// ---------------------------------------------------------------------------
extern "C" void kernel_launch(void* const* d_in, const int* in_sizes, int n_in,
                              void* d_out, int out_size) {
    const float* h      = (const float*)d_in[0];
    const float* weight = (const float*)d_in[1];
    const float* w_comp = (const float*)d_in[2];
    const int*   src    = (const int*)d_in[3];
    const int*   dst    = (const int*)d_in[4];
    const int*   rel    = (const int*)d_in[5];
    float* out = (float*)d_out;          // [h_new (N*64) | h2 (N*64)]
    float* h2  = out + N_NODES * 64;

    static int smem_set = 0;
    if (!smem_set) {
        cudaFuncSetAttribute(mma_scatter_kernel,
                             cudaFuncAttributeMaxDynamicSharedMemorySize, SM_BYTES);
        smem_set = 1;
    }

    // Launch 0: W basis-combination + histogram + scan
    w_hist_scan_kernel<<<256 + NCHUNKS, 256>>>(weight, w_comp, rel);
    // Launch 1: counting sort by relation
    sort_kernel<<<NCHUNKS, 256>>>(src, dst, rel);
    // Launch 2: relu(h) -> out, zero h2
    relu_zero_kernel<<<(N_NODES * 64 / 4 + 255) / 256, 256>>>(
        (const float4*)h, (float4*)out);
    // Launch 3: HMMA edge GEMM + scatter (ncu capture slot = index 3)
    dim3 grid(NC, N_REL);
    mma_scatter_kernel<<<grid, 256, SM_BYTES>>>((const float4*)h, h2);
}

// round 9
// speedup vs baseline: 3.0659x; 1.2005x over previous
#include <cuda_runtime.h>
#include <cuda_bf16.h>

// Problem constants (fixed shapes per reference)
#define N_NODES  100000
#define E_EDGES  1000000
#define N_REL    16
#define N_BASES  8
#define CHUNK    2048
#define NCHUNKS  489
#define NC       18          // segments per relation: 18*16 = 288 CTAs (1 wave @2/SM)
#define TILE_M   128

// SMEM layout (bytes). Rows padded to 144 B (72 bf16) => conflict-free LDSM/LDS.
#define A_STRIDE 144
#define SM_AHI   0                         // 128 x 144 = 18432
#define SM_ALO   18432                     // 18432
#define SM_BHI   36864                     // 64 x 144 = 9216  (B[n][k])
#define SM_BLO   46080                     // 9216
#define SM_DST   55296                     // 128 ints = 512
#define SM_BYTES 55808

// ---------------------------------------------------------------------------
// Device scratch (static only — no cudaMalloc allowed)
// ---------------------------------------------------------------------------
__device__ float d_W[N_REL * 64 * 64];   // W[r][k][o] at r*4096 + k*64 + o
__device__ int   d_cnt[N_REL];           // zero-init; reset each replay
__device__ int   d_done;                 // zero-init; reset each replay
__device__ int   d_off[N_REL + 1];
__device__ int   d_cur[N_REL];
__device__ int2  d_se[E_EDGES];          // edges sorted by relation {src,dst}
// Precomputed split-bf16 copies of h: row n = 64 bf16 = 128 B (line-aligned).
__device__ __align__(128) uint4 d_hhi[N_NODES * 8];
__device__ __align__(128) uint4 d_hlo[N_NODES * 8];

// ---------------------------------------------------------------------------
__device__ __forceinline__ unsigned smem_u32(const void* p) {
    unsigned r;
    asm("{ .reg .u64 t; cvta.to.shared.u64 t, %1; cvt.u32.u64 %0, t; }"
        : "=r"(r) : "l"(p));
    return r;
}
__device__ __forceinline__ unsigned pk2(__nv_bfloat16 a, __nv_bfloat16 b) {
    unsigned short ua = *(unsigned short*)&a, ub = *(unsigned short*)&b;
    return (unsigned)ua | ((unsigned)ub << 16);
}
__device__ __forceinline__ void split2(float x, float y, unsigned& hi, unsigned& lo) {
    __nv_bfloat16 xh = __float2bfloat16_rn(x), yh = __float2bfloat16_rn(y);
    __nv_bfloat16 xl = __float2bfloat16_rn(x - __bfloat162float(xh));
    __nv_bfloat16 yl = __float2bfloat16_rn(y - __bfloat162float(yh));
    hi = pk2(xh, yh);
    lo = pk2(xl, yl);
}
__device__ __forceinline__ void ldsm_x4(unsigned a[4], unsigned addr) {
    asm volatile("ldmatrix.sync.aligned.m8n8.x4.shared.b16 {%0,%1,%2,%3}, [%4];"
                 : "=r"(a[0]), "=r"(a[1]), "=r"(a[2]), "=r"(a[3]) : "r"(addr));
}
__device__ __forceinline__ void ldsm_x2(unsigned b[2], unsigned addr) {
    asm volatile("ldmatrix.sync.aligned.m8n8.x2.shared.b16 {%0,%1}, [%2];"
                 : "=r"(b[0]), "=r"(b[1]) : "r"(addr));
}
__device__ __forceinline__ void mma_bf16(float c[4], const unsigned a[4],
                                         unsigned b0, unsigned b1) {
    asm volatile(
        "mma.sync.aligned.m16n8k16.row.col.f32.bf16.bf16.f32 "
        "{%0,%1,%2,%3}, {%4,%5,%6,%7}, {%8,%9}, {%0,%1,%2,%3};"
        : "+f"(c[0]), "+f"(c[1]), "+f"(c[2]), "+f"(c[3])
        : "r"(a[0]), "r"(a[1]), "r"(a[2]), "r"(a[3]), "r"(b0), "r"(b1));
}

// ---------------------------------------------------------------------------
// L0: fused W basis-combination + rel histogram + scan (proven R6).
// ---------------------------------------------------------------------------
__global__ void w_hist_scan_kernel(const float* __restrict__ weight,
                                   const float* __restrict__ w_comp,
                                   const int* __restrict__ rel) {
    const int tid = threadIdx.x;
    if (blockIdx.x < 256) {
        int idx = blockIdx.x * 256 + tid;
        int im = idx >> 10;
        int rm = (idx >> 6) & 15;
        int om = idx & 63;
        float s = 0.f;
#pragma unroll
        for (int b = 0; b < N_BASES; b++)
            s += w_comp[rm * N_BASES + b] * weight[im * 512 + b * 64 + om];
        d_W[idx] = s;
        return;
    }
    __shared__ int hc[N_REL];
    __shared__ int is_last;
    if (tid < N_REL) hc[tid] = 0;
    if (tid == 0) is_last = 0;
    __syncthreads();
    int base = (blockIdx.x - 256) * CHUNK;
#pragma unroll 2
    for (int j = tid; j < CHUNK; j += 256) {
        int e = base + j;
        if (e < E_EDGES) atomicAdd(&hc[rel[e]], 1);
    }
    __syncthreads();
    if (tid < N_REL) atomicAdd(&d_cnt[tid], hc[tid]);
    __threadfence();
    if (tid == 0) {
        int prev = atomicAdd(&d_done, 1);
        if (prev == NCHUNKS - 1) is_last = 1;
    }
    __syncthreads();
    if (is_last && tid < 32) {
        int c = (tid < N_REL) ? atomicAdd(&d_cnt[tid], 0) : 0;
        int v = c;
#pragma unroll
        for (int d = 1; d < N_REL; d <<= 1) {
            int u = __shfl_up_sync(0xffffffffu, v, d);
            if (tid >= d) v += u;
        }
        if (tid < N_REL) {
            int excl = v - c;
            d_off[tid] = excl;
            d_cur[tid] = excl;
            d_cnt[tid] = 0;
        }
        if (tid == 0) {
            d_off[N_REL] = E_EDGES;
            d_done = 0;
        }
    }
}

// ---------------------------------------------------------------------------
// L1: counting-sort scatter by relation (proven).
// ---------------------------------------------------------------------------
__global__ void sort_kernel(const int* __restrict__ src,
                            const int* __restrict__ dst,
                            const int* __restrict__ rel) {
    __shared__ int hc[N_REL];
    int tid = threadIdx.x;
    if (tid < N_REL) hc[tid] = 0;
    __syncthreads();
    int base = blockIdx.x * CHUNK;
#pragma unroll 2
    for (int j = tid; j < CHUNK; j += 256) {
        int e = base + j;
        if (e < E_EDGES) atomicAdd(&hc[rel[e]], 1);
    }
    __syncthreads();
    if (tid < N_REL) hc[tid] = atomicAdd(&d_cur[tid], hc[tid]);
    __syncthreads();
#pragma unroll 2
    for (int j = tid; j < CHUNK; j += 256) {
        int e = base + j;
        if (e < E_EDGES) {
            int p = atomicAdd(&hc[rel[e]], 1);
            d_se[p] = make_int2(src[e], dst[e]);
        }
    }
}

// ---------------------------------------------------------------------------
// L2: h_new = relu(h); zero h2; AND precompute split-bf16 h_hi/h_lo rows.
// ---------------------------------------------------------------------------
__global__ void relu_split_kernel(const float4* __restrict__ h, float4* out) {
    int i = blockIdx.x * blockDim.x + threadIdx.x;
    const int n4 = N_NODES * 64 / 4;
    if (i >= n4) return;
    float4 v = h[i];
    unsigned h0, l0, h1, l1;
    split2(v.x, v.y, h0, l0);
    split2(v.z, v.w, h1, l1);
    ((uint2*)d_hhi)[i] = make_uint2(h0, h1);
    ((uint2*)d_hlo)[i] = make_uint2(l0, l1);
    v.x = fmaxf(v.x, 0.f);
    v.y = fmaxf(v.y, 0.f);
    v.z = fmaxf(v.z, 0.f);
    v.w = fmaxf(v.w, 0.f);
    out[i] = v;
    out[n4 + i] = make_float4(0.f, 0.f, 0.f, 0.f);
}

// ---------------------------------------------------------------------------
// L3: HMMA tile GEMM + scatter (mma.sync m16n8k16 bf16, split hi/lo).
//   Gather: copy precomputed 128 B hi/lo rows, 8 threads/row (4 lines per
//   warp-LDG => nL=4). B fragments via ldmatrix.x2. Rest as R8 (verified).
// ---------------------------------------------------------------------------
__global__ void __launch_bounds__(256, 2)
mma_scatter_kernel(float* __restrict__ h2) {
    extern __shared__ __align__(16) char dsm[];
    const unsigned sb = smem_u32(dsm);

    const int r = blockIdx.y;
    const int c = blockIdx.x;
    const int start = d_off[r];
    const int cnt   = d_off[r + 1] - start;
    const int seg   = (cnt + NC - 1) / NC;
    const int s0    = start + c * seg;
    const int s1    = min(start + cnt, s0 + seg);

    const int tid  = threadIdx.x;
    const int wid  = tid >> 5;
    const int lane = tid & 31;
    const int g    = lane >> 2;      // fragment row group
    const int t    = lane & 3;       // fragment col group

    // ---- stage B = W[r] as [n][k] bf16 hi/lo, padded rows ----
    for (int idx = tid; idx < 2048; idx += 256) {
        int k2 = idx >> 6;           // k pair index (k = 2*k2, 2*k2+1)
        int o  = idx & 63;           // n
        float x0 = d_W[r * 4096 + (2 * k2) * 64 + o];
        float x1 = d_W[r * 4096 + (2 * k2 + 1) * 64 + o];
        unsigned hi, lo;
        split2(x0, x1, hi, lo);
        *(unsigned*)(dsm + SM_BHI + o * A_STRIDE + k2 * 4) = hi;
        *(unsigned*)(dsm + SM_BLO + o * A_STRIDE + k2 * 4) = lo;
    }
    __syncthreads();
    if (s0 >= s1) return;

    const int rowblk = (wid & 3) * 32;   // this warp's 32 edge-rows
    const int nhalf  = wid >> 2;         // this warp's 32-col half
    // A ldmatrix lane address component (row = lane&15, khalf = lane>>4)
    const unsigned a_lane_off =
        (unsigned)((lane & 15) * A_STRIDE + ((lane >> 4) & 1) * 16);
    // B ldmatrix lane address component (n-row = lane&7, k-half = (lane>>3)&1)
    const unsigned b_lane_off =
        (unsigned)((lane & 7) * A_STRIDE + ((lane >> 3) & 1) * 16);

    const int gseg = tid & 7;            // gather segment (16 B) within row
    const int grow_b = tid >> 3;         // gather row base (0..31), +32 per pass

    for (int tb = s0; tb < s1; tb += TILE_M) {
        const int mt = min(TILE_M, s1 - tb);

        // ---- gather: copy hi/lo rows (4 rows x 128 B per warp-instr) ----
#pragma unroll
        for (int p = 0; p < 4; p++) {
            int grow = p * 32 + grow_b;
            int eidx = min(tb + grow, s1 - 1);
            int2 sd  = __ldg(&d_se[eidx]);
            if (gseg == 0) *(int*)(dsm + SM_DST + grow * 4) = sd.y;
            uint4 Hv = __ldg(d_hhi + (long)sd.x * 8 + gseg);
            uint4 Lv = __ldg(d_hlo + (long)sd.x * 8 + gseg);
            *(uint4*)(dsm + SM_AHI + grow * A_STRIDE + gseg * 16) = Hv;
            *(uint4*)(dsm + SM_ALO + grow * A_STRIDE + gseg * 16) = Lv;
        }
        __syncthreads();

        // ---- MMA: C[2 mtiles][4 nblk][4] ----
        float cf[2][4][4];
#pragma unroll
        for (int m = 0; m < 2; m++)
#pragma unroll
            for (int nb = 0; nb < 4; nb++)
#pragma unroll
                for (int q = 0; q < 4; q++) cf[m][nb][q] = 0.f;

#pragma unroll
        for (int kb = 0; kb < 4; kb++) {
            // B fragments for this kblk via ldmatrix.x2
            unsigned bh[4][2], bl[4][2];
#pragma unroll
            for (int nb = 0; nb < 4; nb++) {
                unsigned baddr = sb
                    + (unsigned)((nhalf * 32 + nb * 8) * A_STRIDE + kb * 32)
                    + b_lane_off;
                ldsm_x2(bh[nb], baddr + SM_BHI);
                ldsm_x2(bl[nb], baddr + SM_BLO);
            }
#pragma unroll
            for (int m = 0; m < 2; m++) {
                unsigned ah[4], al[4];
                unsigned aaddr = sb
                    + (unsigned)((rowblk + m * 16) * A_STRIDE + kb * 32)
                    + a_lane_off;
                ldsm_x4(ah, aaddr + SM_AHI);
                ldsm_x4(al, aaddr + SM_ALO);
#pragma unroll
                for (int nb = 0; nb < 4; nb++) {
                    mma_bf16(cf[m][nb], ah, bh[nb][0], bh[nb][1]);
                    mma_bf16(cf[m][nb], al, bh[nb][0], bh[nb][1]);
                    mma_bf16(cf[m][nb], ah, bl[nb][0], bl[nb][1]);
                }
            }
        }

        // ---- epilogue: shfl-pair -> red.global.add.v4.f32 ----
#pragma unroll
        for (int m = 0; m < 2; m++) {
            int row0 = rowblk + m * 16 + g;      // tile-local edge row
            int row8 = row0 + 8;
            int d0 = *(const int*)(dsm + SM_DST + row0 * 4);
            int d8 = *(const int*)(dsm + SM_DST + row8 * 4);
#pragma unroll
            for (int nb = 0; nb < 4; nb++) {
                float o0 = cf[m][nb][0], o1 = cf[m][nb][1];
                float p0 = cf[m][nb][2], p1 = cf[m][nb][3];
                float o2 = __shfl_down_sync(0xffffffffu, o0, 1);
                float o3 = __shfl_down_sync(0xffffffffu, o1, 1);
                float p2 = __shfl_down_sync(0xffffffffu, p0, 1);
                float p3 = __shfl_down_sync(0xffffffffu, p1, 1);
                if ((t & 1) == 0) {
                    int col = nhalf * 32 + nb * 8 + 2 * t;
                    if (row0 < mt) {
                        float* p = h2 + (long)d0 * 64 + col;
                        asm volatile("red.global.add.v4.f32 [%0], {%1,%2,%3,%4};"
                                     :: "l"(p), "f"(o0), "f"(o1), "f"(o2), "f"(o3)
                                     : "memory");
                    }
                    if (row8 < mt) {
                        float* p = h2 + (long)d8 * 64 + col;
                        asm volatile("red.global.add.v4.f32 [%0], {%1,%2,%3,%4};"
                                     :: "l"(p), "f"(p0), "f"(p1), "f"(p2), "f"(p3)
                                     : "memory");
                    }
                }
            }
        }
        __syncthreads();   // protect A/dst stage before next gather
    }
}

// ---------------------------------------------------------------------------
extern "C" void kernel_launch(void* const* d_in, const int* in_sizes, int n_in,
                              void* d_out, int out_size) {
    const float* h      = (const float*)d_in[0];
    const float* weight = (const float*)d_in[1];
    const float* w_comp = (const float*)d_in[2];
    const int*   src    = (const int*)d_in[3];
    const int*   dst    = (const int*)d_in[4];
    const int*   rel    = (const int*)d_in[5];
    float* out = (float*)d_out;          // [h_new (N*64) | h2 (N*64)]
    float* h2  = out + N_NODES * 64;

    static int smem_set = 0;
    if (!smem_set) {
        cudaFuncSetAttribute(mma_scatter_kernel,
                             cudaFuncAttributeMaxDynamicSharedMemorySize, SM_BYTES);
        smem_set = 1;
    }

    // Launch 0: W basis-combination + histogram + scan
    w_hist_scan_kernel<<<256 + NCHUNKS, 256>>>(weight, w_comp, rel);
    // Launch 1: counting sort by relation
    sort_kernel<<<NCHUNKS, 256>>>(src, dst, rel);
    // Launch 2: relu(h) -> out, zero h2, split h into bf16 hi/lo
    relu_split_kernel<<<(N_NODES * 64 / 4 + 255) / 256, 256>>>(
        (const float4*)h, (float4*)out);
    // Launch 3: HMMA edge GEMM + scatter (ncu capture slot = index 3)
    dim3 grid(NC, N_REL);
    mma_scatter_kernel<<<grid, 256, SM_BYTES>>>(h2);
}

// round 10
// speedup vs baseline: 3.5595x; 1.1610x over previous
#include <cuda_runtime.h>
#include <cuda_bf16.h>

// Problem constants (fixed shapes per reference)
#define N_NODES  100000
#define E_EDGES  1000000
#define N_REL    16
#define N_BASES  8
#define CHUNK    2048
#define NCHUNKS  489
#define NC       18          // segments per relation: 18*16 = 288 CTAs (1 wave @2/SM)
#define TILE_M   128

// SMEM layout (bytes). Rows padded to 144 B => conflict-managed LDSM/LDS.
#define A_STRIDE 144
#define ABUF_SZ  36864       // per buffer: AHI (18432) + ALO (18432)
#define SM_BHI   73728       // B[n][k] hi: 64 x 144
#define SM_BLO   82944
#define SM_DST   92160       // 2 x 128 ints
#define SM_BYTES 93184

// ---------------------------------------------------------------------------
// Device scratch (static only — no cudaMalloc allowed)
// ---------------------------------------------------------------------------
__device__ float d_W[N_REL * 64 * 64];   // W[r][k][o] at r*4096 + k*64 + o
__device__ int   d_cnt[N_REL];           // zero-init; reset each replay
__device__ int   d_done;                 // zero-init; reset each replay
__device__ int   d_off[N_REL + 1];
__device__ int   d_cur[N_REL];
__device__ int2  d_se[E_EDGES];          // edges sorted by relation {src,dst}
// Precomputed split-bf16 copies of h: row n = 64 bf16 = 128 B (line-aligned).
__device__ __align__(128) uint4 d_hhi[N_NODES * 8];
__device__ __align__(128) uint4 d_hlo[N_NODES * 8];

// ---------------------------------------------------------------------------
__device__ __forceinline__ unsigned smem_u32(const void* p) {
    unsigned r;
    asm("{ .reg .u64 t; cvta.to.shared.u64 t, %1; cvt.u32.u64 %0, t; }"
        : "=r"(r) : "l"(p));
    return r;
}
__device__ __forceinline__ unsigned pk2(__nv_bfloat16 a, __nv_bfloat16 b) {
    unsigned short ua = *(unsigned short*)&a, ub = *(unsigned short*)&b;
    return (unsigned)ua | ((unsigned)ub << 16);
}
__device__ __forceinline__ void split2(float x, float y, unsigned& hi, unsigned& lo) {
    __nv_bfloat16 xh = __float2bfloat16_rn(x), yh = __float2bfloat16_rn(y);
    __nv_bfloat16 xl = __float2bfloat16_rn(x - __bfloat162float(xh));
    __nv_bfloat16 yl = __float2bfloat16_rn(y - __bfloat162float(yh));
    hi = pk2(xh, yh);
    lo = pk2(xl, yl);
}
__device__ __forceinline__ void ldsm_x4(unsigned a[4], unsigned addr) {
    asm volatile("ldmatrix.sync.aligned.m8n8.x4.shared.b16 {%0,%1,%2,%3}, [%4];"
                 : "=r"(a[0]), "=r"(a[1]), "=r"(a[2]), "=r"(a[3]) : "r"(addr));
}
__device__ __forceinline__ void ldsm_x2(unsigned b[2], unsigned addr) {
    asm volatile("ldmatrix.sync.aligned.m8n8.x2.shared.b16 {%0,%1}, [%2];"
                 : "=r"(b[0]), "=r"(b[1]) : "r"(addr));
}
__device__ __forceinline__ void mma_bf16(float c[4], const unsigned a[4],
                                         unsigned b0, unsigned b1) {
    asm volatile(
        "mma.sync.aligned.m16n8k16.row.col.f32.bf16.bf16.f32 "
        "{%0,%1,%2,%3}, {%4,%5,%6,%7}, {%8,%9}, {%0,%1,%2,%3};"
        : "+f"(c[0]), "+f"(c[1]), "+f"(c[2]), "+f"(c[3])
        : "r"(a[0]), "r"(a[1]), "r"(a[2]), "r"(a[3]), "r"(b0), "r"(b1));
}

// ---------------------------------------------------------------------------
// L0: fused W basis-combination + rel histogram + scan (proven R6).
// ---------------------------------------------------------------------------
__global__ void w_hist_scan_kernel(const float* __restrict__ weight,
                                   const float* __restrict__ w_comp,
                                   const int* __restrict__ rel) {
    const int tid = threadIdx.x;
    if (blockIdx.x < 256) {
        int idx = blockIdx.x * 256 + tid;
        int im = idx >> 10;
        int rm = (idx >> 6) & 15;
        int om = idx & 63;
        float s = 0.f;
#pragma unroll
        for (int b = 0; b < N_BASES; b++)
            s += w_comp[rm * N_BASES + b] * weight[im * 512 + b * 64 + om];
        d_W[idx] = s;
        return;
    }
    __shared__ int hc[N_REL];
    __shared__ int is_last;
    if (tid < N_REL) hc[tid] = 0;
    if (tid == 0) is_last = 0;
    __syncthreads();
    int base = (blockIdx.x - 256) * CHUNK;
#pragma unroll 2
    for (int j = tid; j < CHUNK; j += 256) {
        int e = base + j;
        if (e < E_EDGES) atomicAdd(&hc[rel[e]], 1);
    }
    __syncthreads();
    if (tid < N_REL) atomicAdd(&d_cnt[tid], hc[tid]);
    __threadfence();
    if (tid == 0) {
        int prev = atomicAdd(&d_done, 1);
        if (prev == NCHUNKS - 1) is_last = 1;
    }
    __syncthreads();
    if (is_last && tid < 32) {
        int c = (tid < N_REL) ? atomicAdd(&d_cnt[tid], 0) : 0;
        int v = c;
#pragma unroll
        for (int d = 1; d < N_REL; d <<= 1) {
            int u = __shfl_up_sync(0xffffffffu, v, d);
            if (tid >= d) v += u;
        }
        if (tid < N_REL) {
            int excl = v - c;
            d_off[tid] = excl;
            d_cur[tid] = excl;
            d_cnt[tid] = 0;
        }
        if (tid == 0) {
            d_off[N_REL] = E_EDGES;
            d_done = 0;
        }
    }
}

// ---------------------------------------------------------------------------
// L1: counting-sort scatter by relation (proven).
// ---------------------------------------------------------------------------
__global__ void sort_kernel(const int* __restrict__ src,
                            const int* __restrict__ dst,
                            const int* __restrict__ rel) {
    __shared__ int hc[N_REL];
    int tid = threadIdx.x;
    if (tid < N_REL) hc[tid] = 0;
    __syncthreads();
    int base = blockIdx.x * CHUNK;
#pragma unroll 2
    for (int j = tid; j < CHUNK; j += 256) {
        int e = base + j;
        if (e < E_EDGES) atomicAdd(&hc[rel[e]], 1);
    }
    __syncthreads();
    if (tid < N_REL) hc[tid] = atomicAdd(&d_cur[tid], hc[tid]);
    __syncthreads();
#pragma unroll 2
    for (int j = tid; j < CHUNK; j += 256) {
        int e = base + j;
        if (e < E_EDGES) {
            int p = atomicAdd(&hc[rel[e]], 1);
            d_se[p] = make_int2(src[e], dst[e]);
        }
    }
}

// ---------------------------------------------------------------------------
// L2: h_new = relu(h); zero h2; AND precompute split-bf16 h_hi/h_lo rows.
// ---------------------------------------------------------------------------
__global__ void relu_split_kernel(const float4* __restrict__ h, float4* out) {
    int i = blockIdx.x * blockDim.x + threadIdx.x;
    const int n4 = N_NODES * 64 / 4;
    if (i >= n4) return;
    float4 v = h[i];
    unsigned h0, l0, h1, l1;
    split2(v.x, v.y, h0, l0);
    split2(v.z, v.w, h1, l1);
    ((uint2*)d_hhi)[i] = make_uint2(h0, h1);
    ((uint2*)d_hlo)[i] = make_uint2(l0, l1);
    v.x = fmaxf(v.x, 0.f);
    v.y = fmaxf(v.y, 0.f);
    v.z = fmaxf(v.z, 0.f);
    v.w = fmaxf(v.w, 0.f);
    out[i] = v;
    out[n4 + i] = make_float4(0.f, 0.f, 0.f, 0.f);
}

// ---------------------------------------------------------------------------
// L3: HMMA tile GEMM + scatter, double-buffered with cp.async.
//   Tile t+1's h rows stream into the idle A buffer via cp.async while tile
//   t runs LDSM/MMA/REDG; indices for t+1 are pre-loaded a tile earlier, so
//   neither the gather nor the index load sits on the critical path.
//   MMA core: 3-product split-bf16 m16n8k16 (verified R8/R9).
// ---------------------------------------------------------------------------
__global__ void __launch_bounds__(256, 2)
mma_scatter_kernel(float* __restrict__ h2) {
    extern __shared__ __align__(16) char dsm[];
    const unsigned sb = smem_u32(dsm);

    const int r = blockIdx.y;
    const int c = blockIdx.x;
    const int start = d_off[r];
    const int cnt   = d_off[r + 1] - start;
    const int seg   = (cnt + NC - 1) / NC;
    const int s0    = start + c * seg;
    const int s1    = min(start + cnt, s0 + seg);

    const int tid  = threadIdx.x;
    const int wid  = tid >> 5;
    const int lane = tid & 31;
    const int g    = lane >> 2;      // fragment row group
    const int t    = lane & 3;       // fragment col group

    // ---- stage B = W[r] as [n][k] bf16 hi/lo, padded rows ----
    for (int idx = tid; idx < 2048; idx += 256) {
        int k2 = idx >> 6;           // k pair index (k = 2*k2, 2*k2+1)
        int o  = idx & 63;           // n
        float x0 = d_W[r * 4096 + (2 * k2) * 64 + o];
        float x1 = d_W[r * 4096 + (2 * k2 + 1) * 64 + o];
        unsigned hi, lo;
        split2(x0, x1, hi, lo);
        *(unsigned*)(dsm + SM_BHI + o * A_STRIDE + k2 * 4) = hi;
        *(unsigned*)(dsm + SM_BLO + o * A_STRIDE + k2 * 4) = lo;
    }
    __syncthreads();
    if (s0 >= s1) return;

    const int rowblk = (wid & 3) * 32;   // this warp's 32 edge-rows
    const int nhalf  = wid >> 2;         // this warp's 32-col half
    const unsigned a_lane_off =
        (unsigned)((lane & 15) * A_STRIDE + ((lane >> 4) & 1) * 16);
    const unsigned b_lane_off =
        (unsigned)((lane & 7) * A_STRIDE + ((lane >> 3) & 1) * 16);

    const int gseg   = tid & 7;          // 16 B segment within a 128 B row
    const int grow_b = tid >> 3;         // row base (0..31), +32 per pass

    const int nt = (s1 - s0 + TILE_M - 1) / TILE_M;

    // index-load for a tile (clamped)
    int2 sd_pf[4];
#pragma unroll
    for (int p = 0; p < 4; p++) {
        int eidx = min(s0 + p * 32 + grow_b, s1 - 1);
        sd_pf[p] = __ldg(&d_se[eidx]);
    }

    // issue cp.async gather for a tile into buffer `buf` using sd[]
    auto issue_gather = [&](const int2 sd[4], int buf) {
        const unsigned abase = sb + (unsigned)(buf * ABUF_SZ);
#pragma unroll
        for (int p = 0; p < 4; p++) {
            int grow = p * 32 + grow_b;
            if (gseg == 0)
                *(int*)(dsm + SM_DST + buf * 512 + grow * 4) = sd[p].y;
            unsigned da = abase + (unsigned)(grow * A_STRIDE + gseg * 16);
            const uint4* gh = d_hhi + (long)sd[p].x * 8 + gseg;
            const uint4* gl = d_hlo + (long)sd[p].x * 8 + gseg;
            asm volatile("cp.async.ca.shared.global [%0], [%1], 16;"
                         :: "r"(da), "l"(gh) : "memory");
            asm volatile("cp.async.ca.shared.global [%0], [%1], 16;"
                         :: "r"(da + 18432u), "l"(gl) : "memory");
        }
        asm volatile("cp.async.commit_group;" ::: "memory");
    };

    // prologue: gather tile 0, pre-load indices for tile 1
    issue_gather(sd_pf, 0);
#pragma unroll
    for (int p = 0; p < 4; p++) {
        int eidx = min(s0 + TILE_M + p * 32 + grow_b, s1 - 1);
        sd_pf[p] = __ldg(&d_se[eidx]);
    }

    for (int it = 0; it < nt; it++) {
        const int tb  = s0 + it * TILE_M;
        const int mt  = min(TILE_M, s1 - tb);
        const int cur = it & 1;

        asm volatile("cp.async.wait_group 0;" ::: "memory");
        __syncthreads();

        // kick off gather for tile it+1; pre-load indices for tile it+2
        if (it + 1 < nt) issue_gather(sd_pf, cur ^ 1);
#pragma unroll
        for (int p = 0; p < 4; p++) {
            int eidx = min(tb + 2 * TILE_M + p * 32 + grow_b, s1 - 1);
            sd_pf[p] = __ldg(&d_se[eidx]);
        }

        // ---- MMA on buffer `cur` ----
        const unsigned abuf = sb + (unsigned)(cur * ABUF_SZ);
        float cf[2][4][4];
#pragma unroll
        for (int m = 0; m < 2; m++)
#pragma unroll
            for (int nb = 0; nb < 4; nb++)
#pragma unroll
                for (int q = 0; q < 4; q++) cf[m][nb][q] = 0.f;

#pragma unroll
        for (int kb = 0; kb < 4; kb++) {
            unsigned bh[4][2], bl[4][2];
#pragma unroll
            for (int nb = 0; nb < 4; nb++) {
                unsigned baddr = sb
                    + (unsigned)((nhalf * 32 + nb * 8) * A_STRIDE + kb * 32)
                    + b_lane_off;
                ldsm_x2(bh[nb], baddr + SM_BHI);
                ldsm_x2(bl[nb], baddr + SM_BLO);
            }
#pragma unroll
            for (int m = 0; m < 2; m++) {
                unsigned ah[4], al[4];
                unsigned aaddr = abuf
                    + (unsigned)((rowblk + m * 16) * A_STRIDE + kb * 32)
                    + a_lane_off;
                ldsm_x4(ah, aaddr);
                ldsm_x4(al, aaddr + 18432u);
#pragma unroll
                for (int nb = 0; nb < 4; nb++) {
                    mma_bf16(cf[m][nb], ah, bh[nb][0], bh[nb][1]);
                    mma_bf16(cf[m][nb], al, bh[nb][0], bh[nb][1]);
                    mma_bf16(cf[m][nb], ah, bl[nb][0], bl[nb][1]);
                }
            }
        }

        // ---- epilogue: shfl-pair -> red.global.add.v4.f32 ----
#pragma unroll
        for (int m = 0; m < 2; m++) {
            int row0 = rowblk + m * 16 + g;
            int row8 = row0 + 8;
            int d0 = *(const int*)(dsm + SM_DST + cur * 512 + row0 * 4);
            int d8 = *(const int*)(dsm + SM_DST + cur * 512 + row8 * 4);
#pragma unroll
            for (int nb = 0; nb < 4; nb++) {
                float o0 = cf[m][nb][0], o1 = cf[m][nb][1];
                float p0 = cf[m][nb][2], p1 = cf[m][nb][3];
                float o2 = __shfl_down_sync(0xffffffffu, o0, 1);
                float o3 = __shfl_down_sync(0xffffffffu, o1, 1);
                float p2 = __shfl_down_sync(0xffffffffu, p0, 1);
                float p3 = __shfl_down_sync(0xffffffffu, p1, 1);
                if ((t & 1) == 0) {
                    int col = nhalf * 32 + nb * 8 + 2 * t;
                    if (row0 < mt) {
                        float* p = h2 + (long)d0 * 64 + col;
                        asm volatile("red.global.add.v4.f32 [%0], {%1,%2,%3,%4};"
                                     :: "l"(p), "f"(o0), "f"(o1), "f"(o2), "f"(o3)
                                     : "memory");
                    }
                    if (row8 < mt) {
                        float* p = h2 + (long)d8 * 64 + col;
                        asm volatile("red.global.add.v4.f32 [%0], {%1,%2,%3,%4};"
                                     :: "l"(p), "f"(p0), "f"(p1), "f"(p2), "f"(p3)
                                     : "memory");
                    }
                }
            }
        }
        // no bottom sync: top-of-loop wait+sync protects both buffers
    }
}

// ---------------------------------------------------------------------------
extern "C" void kernel_launch(void* const* d_in, const int* in_sizes, int n_in,
                              void* d_out, int out_size) {
    const float* h      = (const float*)d_in[0];
    const float* weight = (const float*)d_in[1];
    const float* w_comp = (const float*)d_in[2];
    const int*   src    = (const int*)d_in[3];
    const int*   dst    = (const int*)d_in[4];
    const int*   rel    = (const int*)d_in[5];
    float* out = (float*)d_out;          // [h_new (N*64) | h2 (N*64)]
    float* h2  = out + N_NODES * 64;

    static int smem_set = 0;
    if (!smem_set) {
        cudaFuncSetAttribute(mma_scatter_kernel,
                             cudaFuncAttributeMaxDynamicSharedMemorySize, SM_BYTES);
        smem_set = 1;
    }

    // Launch 0: W basis-combination + histogram + scan
    w_hist_scan_kernel<<<256 + NCHUNKS, 256>>>(weight, w_comp, rel);
    // Launch 1: counting sort by relation
    sort_kernel<<<NCHUNKS, 256>>>(src, dst, rel);
    // Launch 2: relu(h) -> out, zero h2, split h into bf16 hi/lo
    relu_split_kernel<<<(N_NODES * 64 / 4 + 255) / 256, 256>>>(
        (const float4*)h, (float4*)out);
    // Launch 3: HMMA edge GEMM + scatter (ncu capture slot = index 3)
    dim3 grid(NC, N_REL);
    mma_scatter_kernel<<<grid, 256, SM_BYTES>>>(h2);
}

// round 11
// speedup vs baseline: 3.7287x; 1.0475x over previous
#include <cuda_runtime.h>
#include <cuda_bf16.h>

// Problem constants (fixed shapes per reference)
#define N_NODES  100000
#define E_EDGES  1000000
#define N_REL    16
#define N_BASES  8
#define CHUNK    2048
#define NCHUNKS  489
#define NC       18          // segments per relation: 18*16 = 288 CTAs (1 wave @2/SM)
#define TILE_M   128

// SMEM layout (bytes). A rows padded to 144 B; D staging stride 272 B.
#define A_STRIDE 144
#define D_STRIDE 272
#define ABUF_SZ  36864       // per buffer: AHI (18432) + ALO (18432); D reuses it
#define SM_BHI   73728       // B[n][k] hi: 64 x 144
#define SM_BLO   82944
#define SM_DST   92160       // 2 x 128 ints
#define SM_BYTES 93184

// ---------------------------------------------------------------------------
// Device scratch (static only — no cudaMalloc allowed)
// ---------------------------------------------------------------------------
__device__ float d_W[N_REL * 64 * 64];   // W[r][k][o] at r*4096 + k*64 + o
__device__ int   d_cnt[N_REL];           // zero-init; reset each replay
__device__ int   d_done;                 // zero-init; reset each replay
__device__ int   d_off[N_REL + 1];
__device__ int   d_cur[N_REL];
__device__ int2  d_se[E_EDGES];          // edges sorted by relation {src,dst}
// Precomputed split-bf16 copies of h: row n = 64 bf16 = 128 B (line-aligned).
__device__ __align__(128) uint4 d_hhi[N_NODES * 8];
__device__ __align__(128) uint4 d_hlo[N_NODES * 8];

// ---------------------------------------------------------------------------
__device__ __forceinline__ unsigned smem_u32(const void* p) {
    unsigned r;
    asm("{ .reg .u64 t; cvta.to.shared.u64 t, %1; cvt.u32.u64 %0, t; }"
        : "=r"(r) : "l"(p));
    return r;
}
__device__ __forceinline__ unsigned pk2(__nv_bfloat16 a, __nv_bfloat16 b) {
    unsigned short ua = *(unsigned short*)&a, ub = *(unsigned short*)&b;
    return (unsigned)ua | ((unsigned)ub << 16);
}
__device__ __forceinline__ void split2(float x, float y, unsigned& hi, unsigned& lo) {
    __nv_bfloat16 xh = __float2bfloat16_rn(x), yh = __float2bfloat16_rn(y);
    __nv_bfloat16 xl = __float2bfloat16_rn(x - __bfloat162float(xh));
    __nv_bfloat16 yl = __float2bfloat16_rn(y - __bfloat162float(yh));
    hi = pk2(xh, yh);
    lo = pk2(xl, yl);
}
__device__ __forceinline__ void ldsm_x4(unsigned a[4], unsigned addr) {
    asm volatile("ldmatrix.sync.aligned.m8n8.x4.shared.b16 {%0,%1,%2,%3}, [%4];"
                 : "=r"(a[0]), "=r"(a[1]), "=r"(a[2]), "=r"(a[3]) : "r"(addr));
}
__device__ __forceinline__ void mma_bf16(float c[4], const unsigned a[4],
                                         unsigned b0, unsigned b1) {
    asm volatile(
        "mma.sync.aligned.m16n8k16.row.col.f32.bf16.bf16.f32 "
        "{%0,%1,%2,%3}, {%4,%5,%6,%7}, {%8,%9}, {%0,%1,%2,%3};"
        : "+f"(c[0]), "+f"(c[1]), "+f"(c[2]), "+f"(c[3])
        : "r"(a[0]), "r"(a[1]), "r"(a[2]), "r"(a[3]), "r"(b0), "r"(b1));
}

// ---------------------------------------------------------------------------
// L0: fused W basis-combination + rel histogram + scan (proven R6).
// ---------------------------------------------------------------------------
__global__ void w_hist_scan_kernel(const float* __restrict__ weight,
                                   const float* __restrict__ w_comp,
                                   const int* __restrict__ rel) {
    const int tid = threadIdx.x;
    if (blockIdx.x < 256) {
        int idx = blockIdx.x * 256 + tid;
        int im = idx >> 10;
        int rm = (idx >> 6) & 15;
        int om = idx & 63;
        float s = 0.f;
#pragma unroll
        for (int b = 0; b < N_BASES; b++)
            s += w_comp[rm * N_BASES + b] * weight[im * 512 + b * 64 + om];
        d_W[idx] = s;
        return;
    }
    __shared__ int hc[N_REL];
    __shared__ int is_last;
    if (tid < N_REL) hc[tid] = 0;
    if (tid == 0) is_last = 0;
    __syncthreads();
    int base = (blockIdx.x - 256) * CHUNK;
#pragma unroll 2
    for (int j = tid; j < CHUNK; j += 256) {
        int e = base + j;
        if (e < E_EDGES) atomicAdd(&hc[rel[e]], 1);
    }
    __syncthreads();
    if (tid < N_REL) atomicAdd(&d_cnt[tid], hc[tid]);
    __threadfence();
    if (tid == 0) {
        int prev = atomicAdd(&d_done, 1);
        if (prev == NCHUNKS - 1) is_last = 1;
    }
    __syncthreads();
    if (is_last && tid < 32) {
        int c = (tid < N_REL) ? atomicAdd(&d_cnt[tid], 0) : 0;
        int v = c;
#pragma unroll
        for (int d = 1; d < N_REL; d <<= 1) {
            int u = __shfl_up_sync(0xffffffffu, v, d);
            if (tid >= d) v += u;
        }
        if (tid < N_REL) {
            int excl = v - c;
            d_off[tid] = excl;
            d_cur[tid] = excl;
            d_cnt[tid] = 0;
        }
        if (tid == 0) {
            d_off[N_REL] = E_EDGES;
            d_done = 0;
        }
    }
}

// ---------------------------------------------------------------------------
// L1: counting-sort scatter by relation (proven).
// ---------------------------------------------------------------------------
__global__ void sort_kernel(const int* __restrict__ src,
                            const int* __restrict__ dst,
                            const int* __restrict__ rel) {
    __shared__ int hc[N_REL];
    int tid = threadIdx.x;
    if (tid < N_REL) hc[tid] = 0;
    __syncthreads();
    int base = blockIdx.x * CHUNK;
#pragma unroll 2
    for (int j = tid; j < CHUNK; j += 256) {
        int e = base + j;
        if (e < E_EDGES) atomicAdd(&hc[rel[e]], 1);
    }
    __syncthreads();
    if (tid < N_REL) hc[tid] = atomicAdd(&d_cur[tid], hc[tid]);
    __syncthreads();
#pragma unroll 2
    for (int j = tid; j < CHUNK; j += 256) {
        int e = base + j;
        if (e < E_EDGES) {
            int p = atomicAdd(&hc[rel[e]], 1);
            d_se[p] = make_int2(src[e], dst[e]);
        }
    }
}

// ---------------------------------------------------------------------------
// L2: h_new = relu(h); zero h2; AND precompute split-bf16 h_hi/h_lo rows.
// ---------------------------------------------------------------------------
__global__ void relu_split_kernel(const float4* __restrict__ h, float4* out) {
    int i = blockIdx.x * blockDim.x + threadIdx.x;
    const int n4 = N_NODES * 64 / 4;
    if (i >= n4) return;
    float4 v = h[i];
    unsigned h0, l0, h1, l1;
    split2(v.x, v.y, h0, l0);
    split2(v.z, v.w, h1, l1);
    ((uint2*)d_hhi)[i] = make_uint2(h0, h1);
    ((uint2*)d_hlo)[i] = make_uint2(l0, l1);
    v.x = fmaxf(v.x, 0.f);
    v.y = fmaxf(v.y, 0.f);
    v.z = fmaxf(v.z, 0.f);
    v.w = fmaxf(v.w, 0.f);
    out[i] = v;
    out[n4 + i] = make_float4(0.f, 0.f, 0.f, 0.f);
}

// ---------------------------------------------------------------------------
// L3: HMMA tile GEMM + scatter, double-buffered cp.async, row-coalesced
//     scatter: D fragments staged into the consumed A buffer (272 B rows),
//     then each warp reads full 256 B D-rows and issues consecutive
//     red.global.add.v4 into ONE dst row per half-warp (wavefront-minimal).
// ---------------------------------------------------------------------------
__global__ void __launch_bounds__(256, 2)
mma_scatter_kernel(float* __restrict__ h2) {
    extern __shared__ __align__(16) char dsm[];
    const unsigned sb = smem_u32(dsm);

    const int r = blockIdx.y;
    const int c = blockIdx.x;
    const int start = d_off[r];
    const int cnt   = d_off[r + 1] - start;
    const int seg   = (cnt + NC - 1) / NC;
    const int s0    = start + c * seg;
    const int s1    = min(start + cnt, s0 + seg);

    const int tid  = threadIdx.x;
    const int wid  = tid >> 5;
    const int lane = tid & 31;
    const int g    = lane >> 2;      // fragment row group
    const int t    = lane & 3;       // fragment col group

    // ---- stage B = W[r] as [n][k] bf16 hi/lo, padded rows ----
    for (int idx = tid; idx < 2048; idx += 256) {
        int k2 = idx >> 6;           // k pair index (k = 2*k2, 2*k2+1)
        int o  = idx & 63;           // n
        float x0 = d_W[r * 4096 + (2 * k2) * 64 + o];
        float x1 = d_W[r * 4096 + (2 * k2 + 1) * 64 + o];
        unsigned hi, lo;
        split2(x0, x1, hi, lo);
        *(unsigned*)(dsm + SM_BHI + o * A_STRIDE + k2 * 4) = hi;
        *(unsigned*)(dsm + SM_BLO + o * A_STRIDE + k2 * 4) = lo;
    }
    __syncthreads();
    if (s0 >= s1) return;

    const int rowblk = (wid & 3) * 32;   // this warp's 32 edge-rows
    const int nhalf  = wid >> 2;         // this warp's 32-col half
    const unsigned a_lane_off =
        (unsigned)((lane & 15) * A_STRIDE + ((lane >> 4) & 1) * 16);
    // B ldsm_x4 lane offset: matrices (nbA,k0),(nbA,k1),(nbB,k0),(nbB,k1)
    const unsigned b4_lane_off =
        (unsigned)(((lane >> 4) & 1) * 8 * A_STRIDE + (lane & 7) * A_STRIDE
                   + ((lane >> 3) & 1) * 16);

    const int gseg   = tid & 7;          // 16 B segment within a 128 B row
    const int grow_b = tid >> 3;         // row base (0..31), +32 per pass

    const int nt = (s1 - s0 + TILE_M - 1) / TILE_M;

    int2 sd_pf[4];
#pragma unroll
    for (int p = 0; p < 4; p++) {
        int eidx = min(s0 + p * 32 + grow_b, s1 - 1);
        sd_pf[p] = __ldg(&d_se[eidx]);
    }

    auto issue_gather = [&](const int2 sd[4], int buf) {
        const unsigned abase = sb + (unsigned)(buf * ABUF_SZ);
#pragma unroll
        for (int p = 0; p < 4; p++) {
            int grow = p * 32 + grow_b;
            if (gseg == 0)
                *(int*)(dsm + SM_DST + buf * 512 + grow * 4) = sd[p].y;
            unsigned da = abase + (unsigned)(grow * A_STRIDE + gseg * 16);
            const uint4* gh = d_hhi + (long)sd[p].x * 8 + gseg;
            const uint4* gl = d_hlo + (long)sd[p].x * 8 + gseg;
            asm volatile("cp.async.ca.shared.global [%0], [%1], 16;"
                         :: "r"(da), "l"(gh) : "memory");
            asm volatile("cp.async.ca.shared.global [%0], [%1], 16;"
                         :: "r"(da + 18432u), "l"(gl) : "memory");
        }
        asm volatile("cp.async.commit_group;" ::: "memory");
    };

    issue_gather(sd_pf, 0);
#pragma unroll
    for (int p = 0; p < 4; p++) {
        int eidx = min(s0 + TILE_M + p * 32 + grow_b, s1 - 1);
        sd_pf[p] = __ldg(&d_se[eidx]);
    }

    for (int it = 0; it < nt; it++) {
        const int tb  = s0 + it * TILE_M;
        const int mt  = min(TILE_M, s1 - tb);
        const int cur = it & 1;

        asm volatile("cp.async.wait_group 0;" ::: "memory");
        __syncthreads();

        if (it + 1 < nt) issue_gather(sd_pf, cur ^ 1);
#pragma unroll
        for (int p = 0; p < 4; p++) {
            int eidx = min(tb + 2 * TILE_M + p * 32 + grow_b, s1 - 1);
            sd_pf[p] = __ldg(&d_se[eidx]);
        }

        // ---- MMA on buffer `cur` ----
        const unsigned abuf = sb + (unsigned)(cur * ABUF_SZ);
        float cf[2][4][4];
#pragma unroll
        for (int m = 0; m < 2; m++)
#pragma unroll
            for (int nb = 0; nb < 4; nb++)
#pragma unroll
                for (int q = 0; q < 4; q++) cf[m][nb][q] = 0.f;

#pragma unroll
        for (int kb = 0; kb < 4; kb++) {
            // B fragments via ldsm_x4 (nb pairs): regs map
            //   bq[p][0]=(2p,k0) bq[p][1]=(2p,k1) bq[p][2]=(2p+1,k0) bq[p][3]=(2p+1,k1)
            unsigned bh4[2][4], bl4[2][4];
#pragma unroll
            for (int p = 0; p < 2; p++) {
                unsigned baddr = sb
                    + (unsigned)((nhalf * 32 + p * 16) * A_STRIDE + kb * 32)
                    + b4_lane_off;
                ldsm_x4(bh4[p], baddr + SM_BHI);
                ldsm_x4(bl4[p], baddr + SM_BLO);
            }
#pragma unroll
            for (int m = 0; m < 2; m++) {
                unsigned ah[4], al[4];
                unsigned aaddr = abuf
                    + (unsigned)((rowblk + m * 16) * A_STRIDE + kb * 32)
                    + a_lane_off;
                ldsm_x4(ah, aaddr);
                ldsm_x4(al, aaddr + 18432u);
#pragma unroll
                for (int nb = 0; nb < 4; nb++) {
                    unsigned b0h = bh4[nb >> 1][(nb & 1) * 2];
                    unsigned b1h = bh4[nb >> 1][(nb & 1) * 2 + 1];
                    unsigned b0l = bl4[nb >> 1][(nb & 1) * 2];
                    unsigned b1l = bl4[nb >> 1][(nb & 1) * 2 + 1];
                    mma_bf16(cf[m][nb], ah, b0h, b1h);
                    mma_bf16(cf[m][nb], al, b0h, b1h);
                    mma_bf16(cf[m][nb], ah, b0l, b1l);
                }
            }
        }

        // ---- stage D into the consumed A buffer (272 B rows) ----
        __syncthreads();   // all ldsm reads of buffer `cur` complete
#pragma unroll
        for (int m = 0; m < 2; m++) {
            int row0 = rowblk + m * 16 + g;
#pragma unroll
            for (int nb = 0; nb < 4; nb++) {
                int col = nhalf * 32 + nb * 8 + 2 * t;
                *(float2*)(dsm + cur * ABUF_SZ + row0 * D_STRIDE + col * 4) =
                    make_float2(cf[m][nb][0], cf[m][nb][1]);
                *(float2*)(dsm + cur * ABUF_SZ + (row0 + 8) * D_STRIDE + col * 4) =
                    make_float2(cf[m][nb][2], cf[m][nb][3]);
            }
        }
        __syncthreads();

        // ---- row-coalesced scatter: 2 rows per warp-instr ----
        {
            const int seg16 = lane & 15;
            const int rhalf = lane >> 4;
#pragma unroll
            for (int i = 0; i < 8; i++) {
                int row = wid * 16 + 2 * i + rhalf;
                int dn  = *(const int*)(dsm + SM_DST + cur * 512 + row * 4);
                float4 v = *(const float4*)(dsm + cur * ABUF_SZ
                                            + row * D_STRIDE + seg16 * 16);
                if (row < mt) {
                    float* p = h2 + (long)dn * 64 + seg16 * 4;
                    asm volatile("red.global.add.v4.f32 [%0], {%1,%2,%3,%4};"
                                 :: "l"(p), "f"(v.x), "f"(v.y), "f"(v.z), "f"(v.w)
                                 : "memory");
                }
            }
        }
        // top-of-loop wait+sync protects buffers across iterations
    }
}

// ---------------------------------------------------------------------------
extern "C" void kernel_launch(void* const* d_in, const int* in_sizes, int n_in,
                              void* d_out, int out_size) {
    const float* h      = (const float*)d_in[0];
    const float* weight = (const float*)d_in[1];
    const float* w_comp = (const float*)d_in[2];
    const int*   src    = (const int*)d_in[3];
    const int*   dst    = (const int*)d_in[4];
    const int*   rel    = (const int*)d_in[5];
    float* out = (float*)d_out;          // [h_new (N*64) | h2 (N*64)]
    float* h2  = out + N_NODES * 64;

    static int smem_set = 0;
    if (!smem_set) {
        cudaFuncSetAttribute(mma_scatter_kernel,
                             cudaFuncAttributeMaxDynamicSharedMemorySize, SM_BYTES);
        smem_set = 1;
    }

    // Launch 0: W basis-combination + histogram + scan
    w_hist_scan_kernel<<<256 + NCHUNKS, 256>>>(weight, w_comp, rel);
    // Launch 1: counting sort by relation
    sort_kernel<<<NCHUNKS, 256>>>(src, dst, rel);
    // Launch 2: relu(h) -> out, zero h2, split h into bf16 hi/lo
    relu_split_kernel<<<(N_NODES * 64 / 4 + 255) / 256, 256>>>(
        (const float4*)h, (float4*)out);
    // Launch 3: HMMA edge GEMM + row-coalesced scatter (ncu slot = index 3)
    dim3 grid(NC, N_REL);
    mma_scatter_kernel<<<grid, 256, SM_BYTES>>>(h2);
}